// round 15
// baseline (speedup 1.0000x reference)
#include <cuda_runtime.h>
#include <cuda_fp16.h>
#include <cuda_bf16.h>
#include <cstdint>

#define NB   16
#define NIN  256
#define NPHI 256
#define NT   240
#define KH   131584            // 512*257 Hermitian half
#define BK   64
#define NCH  (KH / BK)         // 2056
#define KSP  38                // 32*38 = 1216 = 8*152 exact GB300 waves
#define NS   4
#define OFF_B    16384
#define STG_SZ   47104         // A 16KB + B 30KB
#define SM_WSL   0
#define SM_STG   2048
#define SMEM_TOT (SM_STG + NS * STG_SZ)   // 190464
#define NTHR 640

// ---------------- device scratch (static; no allocation) ----------------
__device__ float2         g_W[NB * 512 * 512];
__device__ unsigned short g_G1[(size_t)NT * KH];     // G fp16 (g * w * 2^-8), [t][kh]
__device__ float          g_Part[(size_t)KSP * 4096 * NT];

// ---------------- helpers ----------------
__device__ __forceinline__ uint32_t smem_u32(const void* p){
    uint32_t a; asm("{ .reg .u64 t; cvta.to.shared.u64 t, %1; cvt.u32.u64 %0, t; }":"=r"(a):"l"(p)); return a;
}
__device__ __forceinline__ void cp16(uint32_t dst, const void* src){
    asm volatile("cp.async.cg.shared.global [%0], [%1], 16;" :: "r"(dst), "l"(src) : "memory");
}
__device__ __forceinline__ void cp8(uint32_t dst, const void* src){
    asm volatile("cp.async.ca.shared.global [%0], [%1], 8;" :: "r"(dst), "l"(src) : "memory");
}
__device__ __forceinline__ void sts128(uint32_t a, uint32_t x, uint32_t y, uint32_t z, uint32_t w){
    asm volatile("st.shared.v4.b32 [%0], {%1,%2,%3,%4};" :: "r"(a), "r"(x), "r"(y), "r"(z), "r"(w) : "memory");
}
__device__ __forceinline__ void ldsm4(uint32_t* d, uint32_t a){
    asm volatile("ldmatrix.sync.aligned.m8n8.x4.shared.b16 {%0,%1,%2,%3}, [%4];"
        : "=r"(d[0]), "=r"(d[1]), "=r"(d[2]), "=r"(d[3]) : "r"(a));
}
__device__ __forceinline__ void mma16816h(float* c, const uint32_t* a, const uint32_t* b){
    asm volatile("mma.sync.aligned.m16n8k16.row.col.f32.f16.f16.f32 "
        "{%0,%1,%2,%3}, {%4,%5,%6,%7}, {%8,%9}, {%0,%1,%2,%3};"
        : "+f"(c[0]), "+f"(c[1]), "+f"(c[2]), "+f"(c[3])
        : "r"(a[0]), "r"(a[1]), "r"(a[2]), "r"(a[3]), "r"(b[0]), "r"(b[1]));
}
__device__ __forceinline__ uint32_t cvt_f16x2(float hi, float lo){
    uint32_t d;
    asm("cvt.rn.f16x2.f32 %0, %1, %2;" : "=r"(d) : "f"(hi), "f"(lo));
    return d;
}
__device__ __forceinline__ void bar_sync(int id){
    asm volatile("bar.sync %0, %1;" :: "r"(id), "n"(NTHR) : "memory");
}
__device__ __forceinline__ void bar_arrive(int id){
    asm volatile("bar.arrive %0, %1;" :: "r"(id), "n"(NTHR) : "memory");
}
__device__ __forceinline__ void bar_sync_prod(){
    asm volatile("bar.sync 9, 128;" ::: "memory");
}

// ---------------- 512-pt radix-2 FFT (validated) ----------------
__device__ __forceinline__ void fft512(float2* buf, int tid, float sign)
{
    #pragma unroll
    for (int s = 0; s < 9; s++) {
        int half = 1 << s;
        int pos  = tid & (half - 1);
        int i0   = ((tid >> s) << (s + 1)) + pos;
        int i1   = i0 + half;
        float ang = sign * 3.14159265358979323846f * (float)pos / (float)half;
        float sv, cv;
        sincosf(ang, &sv, &cv);
        __syncthreads();
        float2 x0 = buf[i0], x1 = buf[i1];
        float tr = x1.x * cv - x1.y * sv;
        float ti = x1.x * sv + x1.y * cv;
        buf[i0] = make_float2(x0.x + tr, x0.y + ti);
        buf[i1] = make_float2(x0.x - tr, x0.y - ti);
    }
    __syncthreads();
}

__global__ void fft_rows_kernel(const float* __restrict__ f)
{
    int a = blockIdx.x, bb = blockIdx.y, tid = threadIdx.x;
    float2* wrow = g_W + ((size_t)bb << 18) + ((size_t)a << 9);
    if (a < 128 || a >= 384) {
        for (int i = tid; i < 512; i += 256) wrow[i] = make_float2(0.f, 0.f);
        return;
    }
    __shared__ float2 buf[512];
    const float* frow = f + (size_t)bb * (NIN * NIN) + (size_t)(a - 128) * NIN;
    for (int i = tid; i < 512; i += 256) {
        float v = (i >= 128 && i < 384) ? frow[i - 128] : 0.f;
        buf[__brev((unsigned)i) >> 23] = make_float2(v, 0.f);
    }
    fft512(buf, tid, -1.0f);
    for (int i = tid; i < 512; i += 256) wrow[i] = buf[i];
}

__global__ void fft_cols_kernel()
{
    int c = blockIdx.x, bb = blockIdx.y, tid = threadIdx.x;
    float2* base = g_W + ((size_t)bb << 18) + c;
    __shared__ float2 buf[512];
    for (int i = tid; i < 512; i += 256)
        buf[__brev((unsigned)i) >> 23] = base[(size_t)i << 9];
    fft512(buf, tid, -1.0f);
    for (int i = tid; i < 512; i += 256) base[(size_t)i << 9] = buf[i];
}

// ---------------- G table: fp16(g_{t+1} * w * 2^-8), [t][kh] ----------------
__global__ void ggen_kernel(const float* __restrict__ fil)
{
    int kh = blockIdx.x * 256 + threadIdx.x;
    if (kh >= KH) return;
    unsigned a = (unsigned)kh / 257u;
    unsigned b = (unsigned)kh - a * 257u;
    float c2 = 2.0f - 4.0f * fil[a * 512u + b];
    float w  = (b == 0u || b == 256u) ? 1.0f : 2.0f;
    float scale = w * 0.00390625f;              // w * 2^-8
    float gp = scale;
    float gc = (c2 - 1.0f) * scale;
    #pragma unroll 4
    for (int t = 0; t < NT; t++) {
        __half h = __float2half_rn(gc);
        g_G1[(size_t)t * KH + kh] = *reinterpret_cast<unsigned short*>(&h);
        float gn = c2 * gc - gp;
        gp = gc; gc = gn;
    }
}

// rotate (cr,ci) by e^{i*step}, where step = uy normally, wd at the b-wrap
#define ROT(cr, ci, b) do { \
    bool wrap_ = ((b) == 256u); \
    float fc_ = wrap_ ? cw : cy, fs_ = wrap_ ? sw_ : sy; \
    float nr_ = (cr) * fc_ - (ci) * fs_; \
    float ni_ = fmaf((cr), fs_, (ci) * fc_); \
    (cr) = nr_; (ci) = ni_; \
    (b) = wrap_ ? 0u : (b) + 1u; \
} while (0)

// ---------------- warp-specialized HMMA GEMM (fp16, BK=64) ----------------
// 640 thr: warps 0-15 consumers (4m x 4n; n = 64,64,64,48), warps 16-19 producers.
__global__ void __launch_bounds__(NTHR, 1)
gemm_kernel(const int* __restrict__ idx0, const int* __restrict__ idx1)
{
    extern __shared__ char smem[];
    const uint32_t sb = smem_u32(smem);
    const int tid = threadIdx.x;
    const int wid = tid >> 5, lane = tid & 31;
    const int mt = blockIdx.x;       // 0..31
    const int ks = blockIdx.y;       // 0..37
    const int bb = mt >> 1;
    const int c0 = (ks * NCH) / KSP, c1 = ((ks + 1) * NCH) / KSP;

    if (wid >= 16) {
        // ================= PRODUCER (4 warps, 128 threads) =================
        const int r = tid - 512;                 // row 0..127
        const int p = ((mt & 1) << 7) + r;
        const unsigned ux = (unsigned)idx0[p], uy = (unsigned)idx1[p];
        int wdi = ((int)ux - 256 * (int)uy) % 512; if (wdi < 0) wdi += 512;
        const unsigned wd = (unsigned)wdi;
        const float TH = 6.2831853071795864769e+00f / 512.0f;
        float cy, sy; sincosf((float)(uy & 511u) * TH, &sy, &cy);
        float cw, sw_; sincosf((float)wd * TH, &sw_, &cw);
        const float2* Wb = g_W + ((size_t)bb << 18);
        const uint32_t rx = (uint32_t)r & 7u;
        const uint32_t wbase = sb + SM_WSL;

        // prologue: W tile for chunk c0
        if (r < 64) {
            int kh = c0 * BK + r;
            unsigned a = (unsigned)kh / 257u, b2 = (unsigned)kh - a * 257u;
            cp8(wbase + (uint32_t)(c0 & 3) * 512u + (uint32_t)r * 8u, Wb + (a << 9) + b2);
        }
        asm volatile("cp.async.commit_group;" ::: "memory");
        asm volatile("cp.async.wait_group 0;" ::: "memory");
        bar_sync_prod();

        for (int c = c0; c < c1; c++) {
            const int s = c & (NS - 1);
            if (c >= c0 + NS) bar_sync(5 + s);
            const uint32_t st = sb + SM_STG + (uint32_t)s * STG_SZ;
            const int k0 = c * BK;

            // B via cp.async: 1920 16B chunks over 128 threads (15 rounds)
            #pragma unroll
            for (int ii = 0; ii < 15; ii++) {
                int i = r + ii * 128;
                int n = i >> 3, cc = i & 7;
                uint32_t d = st + OFF_B + (uint32_t)n * 128u
                           + ((((uint32_t)cc) ^ ((uint32_t)n & 7u)) << 4);
                cp16(d, g_G1 + (size_t)n * KH + k0 + cc * 8);
            }
            // W prefetch for chunk c+1
            if (r < 64 && c + 1 < NCH) {
                int kh = (c + 1) * BK + r;
                unsigned a = (unsigned)kh / 257u, b2 = (unsigned)kh - a * 257u;
                cp8(wbase + (uint32_t)((c + 1) & 3) * 512u + (uint32_t)r * 8u, Wb + (a << 9) + b2);
            }
            asm volatile("cp.async.commit_group;" ::: "memory");

            // A-gen: 64 k-elems for row r; two independent rotation chains.
            {
                const float2* wsm = (const float2*)(smem + SM_WSL + (c & 3) * 512);
                unsigned a1 = (unsigned)k0 / 257u;
                unsigned b1 = (unsigned)k0 - a1 * 257u;
                unsigned ph1 = (a1 * ux + b1 * uy) & 511u;
                float cr1, ci1; __sincosf((float)ph1 * TH, &ci1, &cr1);
                cr1 *= 9.765625e-4f; ci1 *= 9.765625e-4f;
                int k2 = k0 + 32;
                unsigned a2 = (unsigned)k2 / 257u;
                unsigned b2 = (unsigned)k2 - a2 * 257u;
                unsigned ph2 = (a2 * ux + b2 * uy) & 511u;
                float cr2, ci2; __sincosf((float)ph2 * TH, &ci2, &cr2);
                cr2 *= 9.765625e-4f; ci2 *= 9.765625e-4f;

                #pragma unroll
                for (int q = 0; q < 4; q++) {
                    uint32_t hpA[4], hpB[4];
                    #pragma unroll
                    for (int h = 0; h < 4; h++) {
                        const int e = q * 8 + h * 2;
                        float2 wA0 = wsm[e];
                        float mvA0 = wA0.x * cr1 - wA0.y * ci1;
                        ROT(cr1, ci1, b1);
                        float2 wA1 = wsm[e + 1];
                        float mvA1 = wA1.x * cr1 - wA1.y * ci1;
                        ROT(cr1, ci1, b1);
                        float2 wB0 = wsm[32 + e];
                        float mvB0 = wB0.x * cr2 - wB0.y * ci2;
                        ROT(cr2, ci2, b2);
                        float2 wB1 = wsm[32 + e + 1];
                        float mvB1 = wB1.x * cr2 - wB1.y * ci2;
                        ROT(cr2, ci2, b2);
                        hpA[h] = cvt_f16x2(mvA1, mvA0);
                        hpB[h] = cvt_f16x2(mvB1, mvB0);
                    }
                    uint32_t da = st + (uint32_t)r * 128u;
                    sts128(da + ((((uint32_t)q) ^ rx) << 4), hpA[0], hpA[1], hpA[2], hpA[3]);
                    sts128(da + ((((uint32_t)(q + 4)) ^ rx) << 4), hpB[0], hpB[1], hpB[2], hpB[3]);
                }
            }
            asm volatile("cp.async.wait_group 0;" ::: "memory");
            bar_sync_prod();           // W slot visibility among producers
            bar_arrive(1 + s);
        }
    } else {
        // ================= CONSUMER (16 warps = 4m x 4n; n=64,64,64,48) =================
        const int wm = wid & 3, wn = wid >> 2;       // wn 0..3
        const int mrow0 = wm * 32;
        const int n0 = wn * 64;
        const int npairs = (wn < 3) ? 4 : 3;          // 16-wide n units
        const int lrowA = (lane & 7) + ((lane >> 3) & 1) * 8;
        const int lchA  = lane >> 4;
        const int lrowB = (lane & 7) + (lane >> 4) * 8;
        const int lchB  = (lane >> 3) & 1;

        float acc[2][8][4];
        #pragma unroll
        for (int s = 0; s < 2; s++)
            #pragma unroll
            for (int t8 = 0; t8 < 8; t8++)
                #pragma unroll
                for (int q = 0; q < 4; q++) acc[s][t8][q] = 0.f;

        auto baddr = [&](uint32_t st, int ks2, int jp) -> uint32_t {
            int nr_ = n0 + jp * 16 + lrowB;
            return st + OFF_B + (uint32_t)nr_ * 128u
                 + ((((uint32_t)(ks2 * 2 + lchB)) ^ ((uint32_t)nr_ & 7u)) << 4);
        };

        for (int c = c0; c < c1; c++) {
            const int s4 = c & (NS - 1);
            bar_sync(1 + s4);
            const uint32_t st = sb + SM_STG + (uint32_t)s4 * STG_SZ;

            uint32_t Bcur[4], Bnxt[4];
            ldsm4(Bcur, baddr(st, 0, 0));
            #pragma unroll
            for (int ks2 = 0; ks2 < 4; ks2++) {
                uint32_t Ah[2][4];
                #pragma unroll
                for (int s = 0; s < 2; s++) {
                    int row = mrow0 + s * 16 + lrowA;
                    uint32_t a1 = st + (uint32_t)row * 128u
                                + ((((uint32_t)(ks2 * 2 + lchA)) ^ ((uint32_t)row & 7u)) << 4);
                    ldsm4(Ah[s], a1);
                }
                #pragma unroll
                for (int jp = 0; jp < 4; jp++) {
                    if (jp < npairs) {
                        if (jp + 1 < npairs)   ldsm4(Bnxt, baddr(st, ks2, jp + 1));
                        else if (ks2 < 3)      ldsm4(Bnxt, baddr(st, ks2 + 1, 0));
                        mma16816h(acc[0][2 * jp],     Ah[0], Bcur);
                        mma16816h(acc[0][2 * jp + 1], Ah[0], Bcur + 2);
                        mma16816h(acc[1][2 * jp],     Ah[1], Bcur);
                        mma16816h(acc[1][2 * jp + 1], Ah[1], Bcur + 2);
                        #pragma unroll
                        for (int q = 0; q < 4; q++) Bcur[q] = Bnxt[q];
                    }
                }
            }
            bar_arrive(5 + s4);
        }

        // epilogue: write partials
        const int gq = lane >> 2, tg = lane & 3;
        #pragma unroll
        for (int s = 0; s < 2; s++) {
            const int rbase = mt * 128 + mrow0 + s * 16 + gq;
            #pragma unroll
            for (int t8 = 0; t8 < 8; t8++) {
                if (t8 < 2 * npairs) {
                    const int tt = n0 + t8 * 8 + tg * 2;
                    float* d0 = g_Part + ((size_t)ks * 4096 + rbase) * NT + tt;
                    *(float2*)d0 = make_float2(acc[s][t8][0], acc[s][t8][1]);
                    float* d1 = d0 + 8 * NT;
                    *(float2*)d1 = make_float2(acc[s][t8][2], acc[s][t8][3]);
                }
            }
        }
    }
}

// ---------------- reduce over k-splits ----------------
__global__ void reduce_kernel(float* __restrict__ out)
{
    int i = blockIdx.x * 256 + threadIdx.x;   // i = row*240 + t
    if (i >= 4096 * NT) return;
    float s = 0.f;
    #pragma unroll
    for (int k = 0; k < KSP; k++) s += g_Part[(size_t)k * (4096 * NT) + i];
    out[i] = s;
}

extern "C" void kernel_launch(void* const* d_in, const int* in_sizes, int n_in,
                              void* d_out, int out_size)
{
    const float* f   = (const float*)d_in[0];
    const float* fil = (const float*)d_in[1];
    const int*  idx0 = (const int*)d_in[2];
    const int*  idx1 = (const int*)d_in[3];
    float* out = (float*)d_out;

    cudaFuncSetAttribute(gemm_kernel, cudaFuncAttributeMaxDynamicSharedMemorySize, SMEM_TOT);

    fft_rows_kernel<<<dim3(512, NB), 256>>>(f);
    fft_cols_kernel<<<dim3(512, NB), 256>>>();
    ggen_kernel<<<(KH + 255) / 256, 256>>>(fil);
    gemm_kernel<<<dim3(32, KSP), NTHR, SMEM_TOT>>>(idx0, idx1);
    reduce_kernel<<<(4096 * NT + 255) / 256, 256>>>(out);
}

// round 16
// speedup vs baseline: 1.0216x; 1.0216x over previous
#include <cuda_runtime.h>
#include <cuda_fp16.h>
#include <cuda_bf16.h>
#include <cstdint>

#define NB   16
#define NIN  256
#define NPHI 256
#define NT   240
#define KH   131584            // 512*257 Hermitian half
#define BK   64
#define NCH  (KH / BK)         // 2056
#define KSP  19                // 64*19 = 1216 = 4 waves * 304 (2 CTA/SM * 152)
#define NS   2
#define OFF_B    8192
#define STG_SZ   38912         // A 8KB + B 30KB
#define SM_WSL   0             // 4 slots * 64 float2 = 2048 B
#define SM_STG   2048
#define SMEM_TOT (SM_STG + NS * STG_SZ)   // 79872
#define NTHR 320

// ---------------- device scratch (static; no allocation) ----------------
__device__ float2         g_W[NB * 512 * 512];
__device__ unsigned short g_G1[(size_t)NT * KH];     // G fp16 (g * w * 2^-8), [t][kh]
__device__ float          g_Part[(size_t)KSP * 4096 * NT];

// ---------------- helpers ----------------
__device__ __forceinline__ uint32_t smem_u32(const void* p){
    uint32_t a; asm("{ .reg .u64 t; cvta.to.shared.u64 t, %1; cvt.u32.u64 %0, t; }":"=r"(a):"l"(p)); return a;
}
__device__ __forceinline__ void cp16(uint32_t dst, const void* src){
    asm volatile("cp.async.cg.shared.global [%0], [%1], 16;" :: "r"(dst), "l"(src) : "memory");
}
__device__ __forceinline__ void cp8(uint32_t dst, const void* src){
    asm volatile("cp.async.ca.shared.global [%0], [%1], 8;" :: "r"(dst), "l"(src) : "memory");
}
__device__ __forceinline__ void sts128(uint32_t a, uint32_t x, uint32_t y, uint32_t z, uint32_t w){
    asm volatile("st.shared.v4.b32 [%0], {%1,%2,%3,%4};" :: "r"(a), "r"(x), "r"(y), "r"(z), "r"(w) : "memory");
}
__device__ __forceinline__ void ldsm4(uint32_t* d, uint32_t a){
    asm volatile("ldmatrix.sync.aligned.m8n8.x4.shared.b16 {%0,%1,%2,%3}, [%4];"
        : "=r"(d[0]), "=r"(d[1]), "=r"(d[2]), "=r"(d[3]) : "r"(a));
}
__device__ __forceinline__ void mma16816h(float* c, const uint32_t* a, const uint32_t* b){
    asm volatile("mma.sync.aligned.m16n8k16.row.col.f32.f16.f16.f32 "
        "{%0,%1,%2,%3}, {%4,%5,%6,%7}, {%8,%9}, {%0,%1,%2,%3};"
        : "+f"(c[0]), "+f"(c[1]), "+f"(c[2]), "+f"(c[3])
        : "r"(a[0]), "r"(a[1]), "r"(a[2]), "r"(a[3]), "r"(b[0]), "r"(b[1]));
}
__device__ __forceinline__ uint32_t cvt_f16x2(float hi, float lo){
    uint32_t d;
    asm("cvt.rn.f16x2.f32 %0, %1, %2;" : "=r"(d) : "f"(hi), "f"(lo));
    return d;
}
__device__ __forceinline__ void bar_sync(int id){
    asm volatile("bar.sync %0, %1;" :: "r"(id), "n"(NTHR) : "memory");
}
__device__ __forceinline__ void bar_arrive(int id){
    asm volatile("bar.arrive %0, %1;" :: "r"(id), "n"(NTHR) : "memory");
}
__device__ __forceinline__ void bar_sync_prod(){
    asm volatile("bar.sync 9, 64;" ::: "memory");
}

// ---------------- 512-pt radix-2 FFT (validated) ----------------
__device__ __forceinline__ void fft512(float2* buf, int tid, float sign)
{
    #pragma unroll
    for (int s = 0; s < 9; s++) {
        int half = 1 << s;
        int pos  = tid & (half - 1);
        int i0   = ((tid >> s) << (s + 1)) + pos;
        int i1   = i0 + half;
        float ang = sign * 3.14159265358979323846f * (float)pos / (float)half;
        float sv, cv;
        sincosf(ang, &sv, &cv);
        __syncthreads();
        float2 x0 = buf[i0], x1 = buf[i1];
        float tr = x1.x * cv - x1.y * sv;
        float ti = x1.x * sv + x1.y * cv;
        buf[i0] = make_float2(x0.x + tr, x0.y + ti);
        buf[i1] = make_float2(x0.x - tr, x0.y - ti);
    }
    __syncthreads();
}

__global__ void fft_rows_kernel(const float* __restrict__ f)
{
    int a = blockIdx.x, bb = blockIdx.y, tid = threadIdx.x;
    float2* wrow = g_W + ((size_t)bb << 18) + ((size_t)a << 9);
    if (a < 128 || a >= 384) {
        for (int i = tid; i < 512; i += 256) wrow[i] = make_float2(0.f, 0.f);
        return;
    }
    __shared__ float2 buf[512];
    const float* frow = f + (size_t)bb * (NIN * NIN) + (size_t)(a - 128) * NIN;
    for (int i = tid; i < 512; i += 256) {
        float v = (i >= 128 && i < 384) ? frow[i - 128] : 0.f;
        buf[__brev((unsigned)i) >> 23] = make_float2(v, 0.f);
    }
    fft512(buf, tid, -1.0f);
    for (int i = tid; i < 512; i += 256) wrow[i] = buf[i];
}

__global__ void fft_cols_kernel()
{
    int c = blockIdx.x, bb = blockIdx.y, tid = threadIdx.x;
    float2* base = g_W + ((size_t)bb << 18) + c;
    __shared__ float2 buf[512];
    for (int i = tid; i < 512; i += 256)
        buf[__brev((unsigned)i) >> 23] = base[(size_t)i << 9];
    fft512(buf, tid, -1.0f);
    for (int i = tid; i < 512; i += 256) base[(size_t)i << 9] = buf[i];
}

// ---------------- G table: fp16(g_{t+1} * w * 2^-8), [t][kh] ----------------
__global__ void ggen_kernel(const float* __restrict__ fil)
{
    int kh = blockIdx.x * 256 + threadIdx.x;
    if (kh >= KH) return;
    unsigned a = (unsigned)kh / 257u;
    unsigned b = (unsigned)kh - a * 257u;
    float c2 = 2.0f - 4.0f * fil[a * 512u + b];
    float w  = (b == 0u || b == 256u) ? 1.0f : 2.0f;
    float scale = w * 0.00390625f;              // w * 2^-8
    float gp = scale;
    float gc = (c2 - 1.0f) * scale;
    #pragma unroll 4
    for (int t = 0; t < NT; t++) {
        __half h = __float2half_rn(gc);
        g_G1[(size_t)t * KH + kh] = *reinterpret_cast<unsigned short*>(&h);
        float gn = c2 * gc - gp;
        gp = gc; gc = gn;
    }
}

// rotate (cr,ci) by e^{i*step}, step = uy normally, wd at the b-wrap
#define ROT(cr, ci, b) do { \
    bool wrap_ = ((b) == 256u); \
    float fc_ = wrap_ ? cw : cy, fs_ = wrap_ ? sw_ : sy; \
    float nr_ = (cr) * fc_ - (ci) * fs_; \
    float ni_ = fmaf((cr), fs_, (ci) * fc_); \
    (cr) = nr_; (ci) = ni_; \
    (b) = wrap_ ? 0u : (b) + 1u; \
} while (0)

// ---------------- warp-specialized HMMA GEMM (fp16, BK=64, M=64, 2 CTA/SM) ----------------
// 320 thr: warps 0-7 consumers (2m x 4n; n = 64,64,64,48), warps 8-9 producers.
__global__ void __launch_bounds__(NTHR, 2)
gemm_kernel(const int* __restrict__ idx0, const int* __restrict__ idx1)
{
    extern __shared__ char smem[];
    const uint32_t sb = smem_u32(smem);
    const int tid = threadIdx.x;
    const int wid = tid >> 5, lane = tid & 31;
    const int mt = blockIdx.x;       // 0..63 (64-row M tiles)
    const int ks = blockIdx.y;       // 0..18
    const int bb = mt >> 2;
    const int c0 = (ks * NCH) / KSP, c1 = ((ks + 1) * NCH) / KSP;

    if (wid >= 8) {
        // ================= PRODUCER (2 warps, 64 threads) =================
        const int r = tid - 256;                 // row 0..63
        const int p = ((mt & 3) << 6) + r;
        const unsigned ux = (unsigned)idx0[p], uy = (unsigned)idx1[p];
        int wdi = ((int)ux - 256 * (int)uy) % 512; if (wdi < 0) wdi += 512;
        const unsigned wd = (unsigned)wdi;
        const float TH = 6.2831853071795864769e+00f / 512.0f;
        float cy, sy; sincosf((float)(uy & 511u) * TH, &sy, &cy);
        float cw, sw_; sincosf((float)wd * TH, &sw_, &cw);
        const float2* Wb = g_W + ((size_t)bb << 18);
        const uint32_t rx = (uint32_t)r & 7u;
        const uint32_t wbase = sb + SM_WSL;

        // prologue: W tile for chunk c0 (64 kh values)
        {
            int kh = c0 * BK + r;
            unsigned a = (unsigned)kh / 257u, b2 = (unsigned)kh - a * 257u;
            cp8(wbase + (uint32_t)(c0 & 3) * 512u + (uint32_t)r * 8u, Wb + (a << 9) + b2);
        }
        asm volatile("cp.async.commit_group;" ::: "memory");
        asm volatile("cp.async.wait_group 0;" ::: "memory");
        bar_sync_prod();

        for (int c = c0; c < c1; c++) {
            const int s = c & (NS - 1);
            if (c >= c0 + NS) bar_sync(5 + s);
            const uint32_t st = sb + SM_STG + (uint32_t)s * STG_SZ;
            const int k0 = c * BK;

            // B via cp.async: 1920 16B chunks over 64 threads (30 rounds)
            #pragma unroll
            for (int ii = 0; ii < 30; ii++) {
                int i = r + ii * 64;
                int n = i >> 3, cc = i & 7;
                uint32_t d = st + OFF_B + (uint32_t)n * 128u
                           + ((((uint32_t)cc) ^ ((uint32_t)n & 7u)) << 4);
                cp16(d, g_G1 + (size_t)n * KH + k0 + cc * 8);
            }
            // W prefetch for chunk c+1
            if (c + 1 < NCH) {
                int kh = (c + 1) * BK + r;
                unsigned a = (unsigned)kh / 257u, b2 = (unsigned)kh - a * 257u;
                cp8(wbase + (uint32_t)((c + 1) & 3) * 512u + (uint32_t)r * 8u, Wb + (a << 9) + b2);
            }
            asm volatile("cp.async.commit_group;" ::: "memory");

            // A-gen: 64 k-elems for row r; two independent rotation chains.
            {
                const float2* wsm = (const float2*)(smem + SM_WSL + (c & 3) * 512);
                unsigned a1 = (unsigned)k0 / 257u;
                unsigned b1 = (unsigned)k0 - a1 * 257u;
                unsigned ph1 = (a1 * ux + b1 * uy) & 511u;
                float cr1, ci1; __sincosf((float)ph1 * TH, &ci1, &cr1);
                cr1 *= 9.765625e-4f; ci1 *= 9.765625e-4f;
                int k2 = k0 + 32;
                unsigned a2 = (unsigned)k2 / 257u;
                unsigned b2 = (unsigned)k2 - a2 * 257u;
                unsigned ph2 = (a2 * ux + b2 * uy) & 511u;
                float cr2, ci2; __sincosf((float)ph2 * TH, &ci2, &cr2);
                cr2 *= 9.765625e-4f; ci2 *= 9.765625e-4f;

                #pragma unroll
                for (int q = 0; q < 4; q++) {
                    uint32_t hpA[4], hpB[4];
                    #pragma unroll
                    for (int h = 0; h < 4; h++) {
                        const int e = q * 8 + h * 2;
                        float2 wA0 = wsm[e];
                        float mvA0 = wA0.x * cr1 - wA0.y * ci1;
                        ROT(cr1, ci1, b1);
                        float2 wA1 = wsm[e + 1];
                        float mvA1 = wA1.x * cr1 - wA1.y * ci1;
                        ROT(cr1, ci1, b1);
                        float2 wB0 = wsm[32 + e];
                        float mvB0 = wB0.x * cr2 - wB0.y * ci2;
                        ROT(cr2, ci2, b2);
                        float2 wB1 = wsm[32 + e + 1];
                        float mvB1 = wB1.x * cr2 - wB1.y * ci2;
                        ROT(cr2, ci2, b2);
                        hpA[h] = cvt_f16x2(mvA1, mvA0);
                        hpB[h] = cvt_f16x2(mvB1, mvB0);
                    }
                    uint32_t da = st + (uint32_t)r * 128u;
                    sts128(da + ((((uint32_t)q) ^ rx) << 4), hpA[0], hpA[1], hpA[2], hpA[3]);
                    sts128(da + ((((uint32_t)(q + 4)) ^ rx) << 4), hpB[0], hpB[1], hpB[2], hpB[3]);
                }
            }
            asm volatile("cp.async.wait_group 0;" ::: "memory");
            bar_sync_prod();           // W slot visibility among producers
            bar_arrive(1 + s);
        }
    } else {
        // ================= CONSUMER (8 warps = 2m x 4n; n=64,64,64,48) =================
        const int wm = wid & 1, wn = wid >> 1;       // wn 0..3
        const int mrow0 = wm * 32;
        const int n0 = wn * 64;
        const int npairs = (wn < 3) ? 4 : 3;
        const int lrowA = (lane & 7) + ((lane >> 3) & 1) * 8;
        const int lchA  = lane >> 4;
        const int lrowB = (lane & 7) + (lane >> 4) * 8;
        const int lchB  = (lane >> 3) & 1;

        float acc[2][8][4];
        #pragma unroll
        for (int s = 0; s < 2; s++)
            #pragma unroll
            for (int t8 = 0; t8 < 8; t8++)
                #pragma unroll
                for (int q = 0; q < 4; q++) acc[s][t8][q] = 0.f;

        auto baddr = [&](uint32_t st, int ks2, int jp) -> uint32_t {
            int nr_ = n0 + jp * 16 + lrowB;
            return st + OFF_B + (uint32_t)nr_ * 128u
                 + ((((uint32_t)(ks2 * 2 + lchB)) ^ ((uint32_t)nr_ & 7u)) << 4);
        };

        for (int c = c0; c < c1; c++) {
            const int s2 = c & (NS - 1);
            bar_sync(1 + s2);
            const uint32_t st = sb + SM_STG + (uint32_t)s2 * STG_SZ;

            uint32_t Bcur[4], Bnxt[4];
            ldsm4(Bcur, baddr(st, 0, 0));
            #pragma unroll
            for (int ks2 = 0; ks2 < 4; ks2++) {
                uint32_t Ah[2][4];
                #pragma unroll
                for (int s = 0; s < 2; s++) {
                    int row = mrow0 + s * 16 + lrowA;
                    uint32_t a1 = st + (uint32_t)row * 128u
                                + ((((uint32_t)(ks2 * 2 + lchA)) ^ ((uint32_t)row & 7u)) << 4);
                    ldsm4(Ah[s], a1);
                }
                #pragma unroll
                for (int jp = 0; jp < 4; jp++) {
                    if (jp < npairs) {
                        if (jp + 1 < npairs)   ldsm4(Bnxt, baddr(st, ks2, jp + 1));
                        else if (ks2 < 3)      ldsm4(Bnxt, baddr(st, ks2 + 1, 0));
                        mma16816h(acc[0][2 * jp],     Ah[0], Bcur);
                        mma16816h(acc[0][2 * jp + 1], Ah[0], Bcur + 2);
                        mma16816h(acc[1][2 * jp],     Ah[1], Bcur);
                        mma16816h(acc[1][2 * jp + 1], Ah[1], Bcur + 2);
                        #pragma unroll
                        for (int q = 0; q < 4; q++) Bcur[q] = Bnxt[q];
                    }
                }
            }
            bar_arrive(5 + s2);
        }

        // epilogue: write partials
        const int gq = lane >> 2, tg = lane & 3;
        #pragma unroll
        for (int s = 0; s < 2; s++) {
            const int rbase = mt * 64 + mrow0 + s * 16 + gq;
            #pragma unroll
            for (int t8 = 0; t8 < 8; t8++) {
                if (t8 < 2 * npairs) {
                    const int tt = n0 + t8 * 8 + tg * 2;
                    float* d0 = g_Part + ((size_t)ks * 4096 + rbase) * NT + tt;
                    *(float2*)d0 = make_float2(acc[s][t8][0], acc[s][t8][1]);
                    float* d1 = d0 + 8 * NT;
                    *(float2*)d1 = make_float2(acc[s][t8][2], acc[s][t8][3]);
                }
            }
        }
    }
}

// ---------------- reduce over k-splits ----------------
__global__ void reduce_kernel(float* __restrict__ out)
{
    int i = blockIdx.x * 256 + threadIdx.x;   // i = row*240 + t
    if (i >= 4096 * NT) return;
    float s = 0.f;
    #pragma unroll
    for (int k = 0; k < KSP; k++) s += g_Part[(size_t)k * (4096 * NT) + i];
    out[i] = s;
}

extern "C" void kernel_launch(void* const* d_in, const int* in_sizes, int n_in,
                              void* d_out, int out_size)
{
    const float* f   = (const float*)d_in[0];
    const float* fil = (const float*)d_in[1];
    const int*  idx0 = (const int*)d_in[2];
    const int*  idx1 = (const int*)d_in[3];
    float* out = (float*)d_out;

    cudaFuncSetAttribute(gemm_kernel, cudaFuncAttributeMaxDynamicSharedMemorySize, SMEM_TOT);

    fft_rows_kernel<<<dim3(512, NB), 256>>>(f);
    fft_cols_kernel<<<dim3(512, NB), 256>>>();
    ggen_kernel<<<(KH + 255) / 256, 256>>>(fil);
    gemm_kernel<<<dim3(64, KSP), NTHR, SMEM_TOT>>>(idx0, idx1);
    reduce_kernel<<<(4096 * NT + 255) / 256, 256>>>(out);
}

// round 17
// speedup vs baseline: 1.1564x; 1.1320x over previous
#include <cuda_runtime.h>
#include <cuda_fp16.h>
#include <cuda_bf16.h>
#include <cstdint>

#define NB   16
#define NIN  256
#define NPHI 256
#define NT   240
#define KH   131584            // 512*257 Hermitian half
#define BK   64
#define NCH  (KH / BK)         // 2056
#define KSP  19                // 32*19 = 608 = 4 exact waves on 152 SMs
#define NS   4
#define OFF_B    16384
#define STG_SZ   47104         // A 16KB + B 30KB
#define SM_WSL   0
#define SM_STG   2048
#define SMEM_TOT (SM_STG + NS * STG_SZ)   // 190464

// ---------------- device scratch (static; no allocation) ----------------
__device__ float2         g_W[NB * 512 * 512];
__device__ unsigned short g_G1[(size_t)NT * KH];     // G fp16 (g * w * 2^-8), [t][kh]
__device__ float          g_Part[(size_t)KSP * 4096 * NT];

// ---------------- helpers ----------------
__device__ __forceinline__ uint32_t smem_u32(const void* p){
    uint32_t a; asm("{ .reg .u64 t; cvta.to.shared.u64 t, %1; cvt.u32.u64 %0, t; }":"=r"(a):"l"(p)); return a;
}
__device__ __forceinline__ void cp16(uint32_t dst, const void* src){
    asm volatile("cp.async.cg.shared.global [%0], [%1], 16;" :: "r"(dst), "l"(src) : "memory");
}
__device__ __forceinline__ void cp8(uint32_t dst, const void* src){
    asm volatile("cp.async.ca.shared.global [%0], [%1], 8;" :: "r"(dst), "l"(src) : "memory");
}
__device__ __forceinline__ void sts128(uint32_t a, uint32_t x, uint32_t y, uint32_t z, uint32_t w){
    asm volatile("st.shared.v4.b32 [%0], {%1,%2,%3,%4};" :: "r"(a), "r"(x), "r"(y), "r"(z), "r"(w) : "memory");
}
__device__ __forceinline__ void ldsm4(uint32_t* d, uint32_t a){
    asm volatile("ldmatrix.sync.aligned.m8n8.x4.shared.b16 {%0,%1,%2,%3}, [%4];"
        : "=r"(d[0]), "=r"(d[1]), "=r"(d[2]), "=r"(d[3]) : "r"(a));
}
__device__ __forceinline__ void mma16816h(float* c, const uint32_t* a, const uint32_t* b){
    asm volatile("mma.sync.aligned.m16n8k16.row.col.f32.f16.f16.f32 "
        "{%0,%1,%2,%3}, {%4,%5,%6,%7}, {%8,%9}, {%0,%1,%2,%3};"
        : "+f"(c[0]), "+f"(c[1]), "+f"(c[2]), "+f"(c[3])
        : "r"(a[0]), "r"(a[1]), "r"(a[2]), "r"(a[3]), "r"(b[0]), "r"(b[1]));
}
__device__ __forceinline__ uint32_t cvt_f16x2(float hi, float lo){
    uint32_t d;
    asm("cvt.rn.f16x2.f32 %0, %1, %2;" : "=r"(d) : "f"(hi), "f"(lo));
    return d;
}
__device__ __forceinline__ void bar_sync(int id){
    asm volatile("bar.sync %0, 512;" :: "r"(id) : "memory");
}
__device__ __forceinline__ void bar_arrive(int id){
    asm volatile("bar.arrive %0, 512;" :: "r"(id) : "memory");
}
__device__ __forceinline__ void bar_sync_prod(){
    asm volatile("bar.sync 9, 128;" ::: "memory");
}

// ---------------- 512-pt radix-2 FFT (validated; fast twiddles) ----------------
__device__ __forceinline__ void fft512(float2* buf, int tid, float sign)
{
    #pragma unroll
    for (int s = 0; s < 9; s++) {
        int half = 1 << s;
        int pos  = tid & (half - 1);
        int i0   = ((tid >> s) << (s + 1)) + pos;
        int i1   = i0 + half;
        float ang = sign * 3.14159265358979323846f * (float)pos / (float)half;
        float sv, cv;
        __sincosf(ang, &sv, &cv);
        __syncthreads();
        float2 x0 = buf[i0], x1 = buf[i1];
        float tr = x1.x * cv - x1.y * sv;
        float ti = x1.x * sv + x1.y * cv;
        buf[i0] = make_float2(x0.x + tr, x0.y + ti);
        buf[i1] = make_float2(x0.x - tr, x0.y - ti);
    }
    __syncthreads();
}

__global__ void fft_rows_kernel(const float* __restrict__ f)
{
    int a = blockIdx.x, bb = blockIdx.y, tid = threadIdx.x;
    float2* wrow = g_W + ((size_t)bb << 18) + ((size_t)a << 9);
    if (a < 128 || a >= 384) {
        for (int i = tid; i < 512; i += 256) wrow[i] = make_float2(0.f, 0.f);
        return;
    }
    __shared__ float2 buf[512];
    const float* frow = f + (size_t)bb * (NIN * NIN) + (size_t)(a - 128) * NIN;
    for (int i = tid; i < 512; i += 256) {
        float v = (i >= 128 && i < 384) ? frow[i - 128] : 0.f;
        buf[__brev((unsigned)i) >> 23] = make_float2(v, 0.f);
    }
    fft512(buf, tid, -1.0f);
    for (int i = tid; i < 512; i += 256) wrow[i] = buf[i];
}

__global__ void fft_cols_kernel()
{
    int c = blockIdx.x, bb = blockIdx.y, tid = threadIdx.x;
    float2* base = g_W + ((size_t)bb << 18) + c;
    __shared__ float2 buf[512];
    for (int i = tid; i < 512; i += 256)
        buf[__brev((unsigned)i) >> 23] = base[(size_t)i << 9];
    fft512(buf, tid, -1.0f);
    for (int i = tid; i < 512; i += 256) base[(size_t)i << 9] = buf[i];
}

// ---------------- G table: fp16(g_{t+1} * w * 2^-8), [t][kh] ----------------
__global__ void ggen_kernel(const float* __restrict__ fil)
{
    int kh = blockIdx.x * 256 + threadIdx.x;
    if (kh >= KH) return;
    unsigned a = (unsigned)kh / 257u;
    unsigned b = (unsigned)kh - a * 257u;
    float c2 = 2.0f - 4.0f * fil[a * 512u + b];
    float w  = (b == 0u || b == 256u) ? 1.0f : 2.0f;
    float scale = w * 0.00390625f;              // w * 2^-8
    float gp = scale;
    float gc = (c2 - 1.0f) * scale;
    #pragma unroll 4
    for (int t = 0; t < NT; t++) {
        __half h = __float2half_rn(gc);
        g_G1[(size_t)t * KH + kh] = *reinterpret_cast<unsigned short*>(&h);
        float gn = c2 * gc - gp;
        gp = gc; gc = gn;
    }
}

// rotate (cr,ci) by e^{i*step}, step = uy normally, wd at the b-wrap
#define ROT(cr, ci, b) do { \
    bool wrap_ = ((b) == 256u); \
    float fc_ = wrap_ ? cw : cy, fs_ = wrap_ ? sw_ : sy; \
    float nr_ = (cr) * fc_ - (ci) * fs_; \
    float ni_ = fmaf((cr), fs_, (ci) * fc_); \
    (cr) = nr_; (ci) = ni_; \
    (b) = wrap_ ? 0u : (b) + 1u; \
} while (0)

// ---------------- warp-specialized HMMA GEMM (fp16, BK=64) ----------------
// 512 thr: warps 0-11 consumers (4m x 3n, n=80 each), warps 12-15 producers.
__global__ void __launch_bounds__(512, 1)
gemm_kernel(const int* __restrict__ idx0, const int* __restrict__ idx1)
{
    extern __shared__ char smem[];
    const uint32_t sb = smem_u32(smem);
    const int tid = threadIdx.x;
    const int wid = tid >> 5, lane = tid & 31;
    const int mt = blockIdx.x;       // 0..31
    const int ks = blockIdx.y;       // 0..18
    const int bb = mt >> 1;
    const int c0 = (ks * NCH) / KSP, c1 = ((ks + 1) * NCH) / KSP;

    if (wid >= 12) {
        // ================= PRODUCER (4 warps, 128 threads) =================
        const int r = tid - 384;                 // row 0..127
        const int p = ((mt & 1) << 7) + r;
        const unsigned ux = (unsigned)idx0[p], uy = (unsigned)idx1[p];
        int wdi = ((int)ux - 256 * (int)uy) % 512; if (wdi < 0) wdi += 512;
        const unsigned wd = (unsigned)wdi;
        const float TH = 6.2831853071795864769e+00f / 512.0f;
        float cy, sy; sincosf((float)(uy & 511u) * TH, &sy, &cy);
        float cw, sw_; sincosf((float)wd * TH, &sw_, &cw);
        const float2* Wb = g_W + ((size_t)bb << 18);
        const uint32_t rx = (uint32_t)r & 7u;
        const uint32_t wbase = sb + SM_WSL;

        // prologue: W tile for chunk c0
        if (r < 64) {
            int kh = c0 * BK + r;
            unsigned a = (unsigned)kh / 257u, b2 = (unsigned)kh - a * 257u;
            cp8(wbase + (uint32_t)(c0 & 3) * 512u + (uint32_t)r * 8u, Wb + (a << 9) + b2);
        }
        asm volatile("cp.async.commit_group;" ::: "memory");
        asm volatile("cp.async.wait_group 0;" ::: "memory");
        bar_sync_prod();

        for (int c = c0; c < c1; c++) {
            const int s = c & (NS - 1);
            if (c >= c0 + NS) bar_sync(5 + s);
            const uint32_t st = sb + SM_STG + (uint32_t)s * STG_SZ;
            const int k0 = c * BK;

            // B via cp.async: 1920 16B chunks over 128 threads (15 rounds)
            #pragma unroll
            for (int ii = 0; ii < 15; ii++) {
                int i = r + ii * 128;
                int n = i >> 3, cc = i & 7;
                uint32_t d = st + OFF_B + (uint32_t)n * 128u
                           + ((((uint32_t)cc) ^ ((uint32_t)n & 7u)) << 4);
                cp16(d, g_G1 + (size_t)n * KH + k0 + cc * 8);
            }
            // W prefetch for chunk c+1
            if (r < 64 && c + 1 < NCH) {
                int kh = (c + 1) * BK + r;
                unsigned a = (unsigned)kh / 257u, b2 = (unsigned)kh - a * 257u;
                cp8(wbase + (uint32_t)((c + 1) & 3) * 512u + (uint32_t)r * 8u, Wb + (a << 9) + b2);
            }
            asm volatile("cp.async.commit_group;" ::: "memory");

            // A-gen: 64 k-elems for row r; two independent rotation chains.
            {
                const float2* wsm = (const float2*)(smem + SM_WSL + (c & 3) * 512);
                unsigned a1 = (unsigned)k0 / 257u;
                unsigned b1 = (unsigned)k0 - a1 * 257u;
                unsigned ph1 = (a1 * ux + b1 * uy) & 511u;
                float cr1, ci1; __sincosf((float)ph1 * TH, &ci1, &cr1);
                cr1 *= 9.765625e-4f; ci1 *= 9.765625e-4f;
                int k2 = k0 + 32;
                unsigned a2 = (unsigned)k2 / 257u;
                unsigned b2 = (unsigned)k2 - a2 * 257u;
                unsigned ph2 = (a2 * ux + b2 * uy) & 511u;
                float cr2, ci2; __sincosf((float)ph2 * TH, &ci2, &cr2);
                cr2 *= 9.765625e-4f; ci2 *= 9.765625e-4f;

                #pragma unroll
                for (int q = 0; q < 4; q++) {
                    uint32_t hpA[4], hpB[4];
                    #pragma unroll
                    for (int h = 0; h < 4; h++) {
                        const int e = q * 8 + h * 2;
                        float2 wA0 = wsm[e];
                        float mvA0 = wA0.x * cr1 - wA0.y * ci1;
                        ROT(cr1, ci1, b1);
                        float2 wA1 = wsm[e + 1];
                        float mvA1 = wA1.x * cr1 - wA1.y * ci1;
                        ROT(cr1, ci1, b1);
                        float2 wB0 = wsm[32 + e];
                        float mvB0 = wB0.x * cr2 - wB0.y * ci2;
                        ROT(cr2, ci2, b2);
                        float2 wB1 = wsm[32 + e + 1];
                        float mvB1 = wB1.x * cr2 - wB1.y * ci2;
                        ROT(cr2, ci2, b2);
                        hpA[h] = cvt_f16x2(mvA1, mvA0);
                        hpB[h] = cvt_f16x2(mvB1, mvB0);
                    }
                    uint32_t da = st + (uint32_t)r * 128u;
                    sts128(da + ((((uint32_t)q) ^ rx) << 4), hpA[0], hpA[1], hpA[2], hpA[3]);
                    sts128(da + ((((uint32_t)(q + 4)) ^ rx) << 4), hpB[0], hpB[1], hpB[2], hpB[3]);
                }
            }
            asm volatile("cp.async.wait_group 0;" ::: "memory");
            bar_sync_prod();           // W slot visibility among producers
            bar_arrive(1 + s);
        }
    } else {
        // ================= CONSUMER (12 warps = 4m x 3n, n=80) =================
        const int wm = wid & 3, wn = wid >> 2;       // wn 0..2
        const int mrow0 = wm * 32;
        const int n0 = wn * 80;
        const int lrowA = (lane & 7) + ((lane >> 3) & 1) * 8;
        const int lchA  = lane >> 4;
        const int lrowB = (lane & 7) + (lane >> 4) * 8;
        const int lchB  = (lane >> 3) & 1;

        float acc[2][10][4];
        #pragma unroll
        for (int s = 0; s < 2; s++)
            #pragma unroll
            for (int t8 = 0; t8 < 10; t8++)
                #pragma unroll
                for (int q = 0; q < 4; q++) acc[s][t8][q] = 0.f;

        auto baddr = [&](uint32_t st, int ks2, int jp) -> uint32_t {
            int nr_ = n0 + jp * 16 + lrowB;
            return st + OFF_B + (uint32_t)nr_ * 128u
                 + ((((uint32_t)(ks2 * 2 + lchB)) ^ ((uint32_t)nr_ & 7u)) << 4);
        };

        for (int c = c0; c < c1; c++) {
            const int s4 = c & (NS - 1);
            bar_sync(1 + s4);
            const uint32_t st = sb + SM_STG + (uint32_t)s4 * STG_SZ;

            uint32_t B[2][4];
            uint32_t Ah[2][4];
            ldsm4(B[0], baddr(st, 0, 0));      // prime B pipeline
            // flattened 20 steps: ks2 = s5/5, jp = s5%5; B double-buffered
            #pragma unroll
            for (int s5 = 0; s5 < 20; s5++) {
                const int ks2 = s5 / 5, jp = s5 % 5;
                if (jp == 0) {
                    #pragma unroll
                    for (int s = 0; s < 2; s++) {
                        int row = mrow0 + s * 16 + lrowA;
                        uint32_t a1 = st + (uint32_t)row * 128u
                                    + ((((uint32_t)(ks2 * 2 + lchA)) ^ ((uint32_t)row & 7u)) << 4);
                        ldsm4(Ah[s], a1);
                    }
                }
                if (s5 + 1 < 20)
                    ldsm4(B[(s5 + 1) & 1], baddr(st, (s5 + 1) / 5, (s5 + 1) % 5));
                const uint32_t* Bc = B[s5 & 1];
                mma16816h(acc[0][2 * jp],     Ah[0], Bc);
                mma16816h(acc[0][2 * jp + 1], Ah[0], Bc + 2);
                mma16816h(acc[1][2 * jp],     Ah[1], Bc);
                mma16816h(acc[1][2 * jp + 1], Ah[1], Bc + 2);
            }
            bar_arrive(5 + s4);
        }

        // epilogue: write partials
        const int gq = lane >> 2, tg = lane & 3;
        #pragma unroll
        for (int s = 0; s < 2; s++) {
            const int rbase = mt * 128 + mrow0 + s * 16 + gq;
            #pragma unroll
            for (int t8 = 0; t8 < 10; t8++) {
                const int tt = n0 + t8 * 8 + tg * 2;
                float* d0 = g_Part + ((size_t)ks * 4096 + rbase) * NT + tt;
                *(float2*)d0 = make_float2(acc[s][t8][0], acc[s][t8][1]);
                float* d1 = d0 + 8 * NT;
                *(float2*)d1 = make_float2(acc[s][t8][2], acc[s][t8][3]);
            }
        }
    }
}

// ---------------- reduce over k-splits ----------------
__global__ void reduce_kernel(float* __restrict__ out)
{
    int i = blockIdx.x * 256 + threadIdx.x;   // i = row*240 + t
    if (i >= 4096 * NT) return;
    float s = 0.f;
    #pragma unroll
    for (int k = 0; k < KSP; k++) s += g_Part[(size_t)k * (4096 * NT) + i];
    out[i] = s;
}

extern "C" void kernel_launch(void* const* d_in, const int* in_sizes, int n_in,
                              void* d_out, int out_size)
{
    const float* f   = (const float*)d_in[0];
    const float* fil = (const float*)d_in[1];
    const int*  idx0 = (const int*)d_in[2];
    const int*  idx1 = (const int*)d_in[3];
    float* out = (float*)d_out;

    cudaFuncSetAttribute(gemm_kernel, cudaFuncAttributeMaxDynamicSharedMemorySize, SMEM_TOT);

    fft_rows_kernel<<<dim3(512, NB), 256>>>(f);
    fft_cols_kernel<<<dim3(512, NB), 256>>>();
    ggen_kernel<<<(KH + 255) / 256, 256>>>(fil);
    gemm_kernel<<<dim3(32, KSP), 512, SMEM_TOT>>>(idx0, idx1);
    reduce_kernel<<<(4096 * NT + 255) / 256, 256>>>(out);
}